// round 6
// baseline (speedup 1.0000x reference)
#include <cuda_runtime.h>
#include <cuda_bf16.h>
#include <cstdint>
#include <cstddef>

#define NB 8
#define NL 4096
#define ND 1024
#define NROWS (NB*NL)   // 32768

// ---- scratch (device globals; no allocation allowed) ----
__device__ float    g_Q[(size_t)NROWS * ND];
__device__ float    g_K[(size_t)NROWS * ND];
__device__ float    g_V[(size_t)NROWS * ND];      // becomes U (=T@Vb) in place
__device__ float    g_O[(size_t)NROWS * ND];
__device__ float    g_beta[NROWS];
__device__ float    g_A[(size_t)NB * 64 * 64 * 64];
// fragment-ordered pre-split operands for the scan
__device__ uint32_t g_Qf [(size_t)NROWS * ND];        // Q hi (tf32 bits), frag order
__device__ uint32_t g_Qfl[(size_t)NROWS * ND / 2];    // Q lo (bf16x2)
__device__ uint32_t g_Wf [(size_t)NROWS * ND];        // -W hi
__device__ uint32_t g_Wfl[(size_t)NROWS * ND / 2];    // -W lo
__device__ uint32_t g_Ktf [(size_t)NROWS * ND];       // K^T hi (b-frag order)
__device__ uint32_t g_Ktfl[(size_t)NROWS * ND / 2];   // K^T lo

__device__ __forceinline__ uint32_t f2tf32(float x) {
    uint32_t r;
    asm("cvt.rna.tf32.f32 %0, %1;" : "=r"(r) : "f"(x));
    return r;
}
__device__ __forceinline__ void tsplit(float x, uint32_t& h, uint32_t& l) {
    h = f2tf32(x);
    l = f2tf32(x - __uint_as_float(h));
}
__device__ __forceinline__ unsigned short bf16bits(float x) {
    return __bfloat16_as_ushort(__float2bfloat16(x));
}
__device__ __forceinline__ float bf16f(unsigned short u) {
    return __uint_as_float(((uint32_t)u) << 16);
}

#define MMA_TF32(d, a, b0, b1) \
    asm volatile("mma.sync.aligned.m16n8k8.row.col.f32.tf32.tf32.f32 " \
        "{%0,%1,%2,%3}, {%4,%5,%6,%7}, {%8,%9}, {%0,%1,%2,%3};" \
        : "+f"((d)[0]), "+f"((d)[1]), "+f"((d)[2]), "+f"((d)[3]) \
        : "r"((a)[0]), "r"((a)[1]), "r"((a)[2]), "r"((a)[3]), "r"(b0), "r"(b1))

// =====================================================================
// tf32 mma.sync GEMM: C(MxN) = A(MxK) @ W(NxK)^T + bias(N)
// =====================================================================
#define GPITCH 36
#define GASZ   (128 * GPITCH)
#define GSMEM  (4 * GASZ * 4)

__global__ void __launch_bounds__(256, 1) gemm_mma(
    const float* __restrict__ A, const float* __restrict__ Wm,
    const float* __restrict__ bias, float* __restrict__ C,
    int M, int N, int K)
{
    extern __shared__ uint32_t smg[];
    const int t    = threadIdx.x;
    const int wid  = t >> 5;
    const int lane = t & 31;
    const int wm   = wid & 1;
    const int wn   = wid >> 1;
    const int m0   = blockIdx.y * 128;
    const int n0   = blockIdx.x * 128;
    const int lr   = lane >> 2;
    const int lc   = lane & 3;

    const float* Ap = A  + (size_t)m0 * K;
    const float* Bp = Wm + (size_t)n0 * K;

    float acc[4][4][4];
#pragma unroll
    for (int i = 0; i < 4; i++)
#pragma unroll
        for (int j = 0; j < 4; j++)
#pragma unroll
            for (int x = 0; x < 4; x++) acc[i][j][x] = 0.f;

#pragma unroll
    for (int i = 0; i < 4; i++) {
        int idx = t + i * 256;
        int r = idx >> 3, c4 = idx & 7;
        float4 va = *(const float4*)(Ap + (size_t)r * K + c4 * 4);
        uint32_t* dst = &smg[r * GPITCH + c4 * 4];
        dst[0] = f2tf32(va.x); dst[1] = f2tf32(va.y);
        dst[2] = f2tf32(va.z); dst[3] = f2tf32(va.w);
        float4 vb = *(const float4*)(Bp + (size_t)r * K + c4 * 4);
        uint32_t* dstb = &smg[GASZ + r * GPITCH + c4 * 4];
        dstb[0] = f2tf32(vb.x); dstb[1] = f2tf32(vb.y);
        dstb[2] = f2tf32(vb.z); dstb[3] = f2tf32(vb.w);
    }
    __syncthreads();

    const int nkt = K >> 5;
    for (int kt = 0; kt < nkt; kt++) {
        const int cur = kt & 1;
        float4 ra[4], rb[4];
        if (kt + 1 < nkt) {
            const int ko = (kt + 1) * 32;
#pragma unroll
            for (int i = 0; i < 4; i++) {
                int idx = t + i * 256;
                int r = idx >> 3, c4 = idx & 7;
                ra[i] = *(const float4*)(Ap + (size_t)r * K + ko + c4 * 4);
                rb[i] = *(const float4*)(Bp + (size_t)r * K + ko + c4 * 4);
            }
        }
        const uint32_t* As = smg + cur * 2 * GASZ;
        const uint32_t* Bs = As + GASZ;
#pragma unroll
        for (int k8 = 0; k8 < 4; k8++) {
            const int kb = k8 * 8 + lc;
            uint32_t af[4][4], bf[4][2];
#pragma unroll
            for (int mt = 0; mt < 4; mt++) {
                int r = wm * 64 + mt * 16 + lr;
                af[mt][0] = As[r * GPITCH + kb];
                af[mt][1] = As[(r + 8) * GPITCH + kb];
                af[mt][2] = As[r * GPITCH + kb + 4];
                af[mt][3] = As[(r + 8) * GPITCH + kb + 4];
            }
#pragma unroll
            for (int nt = 0; nt < 4; nt++) {
                int n = wn * 32 + nt * 8 + lr;
                bf[nt][0] = Bs[n * GPITCH + kb];
                bf[nt][1] = Bs[n * GPITCH + kb + 4];
            }
#pragma unroll
            for (int mt = 0; mt < 4; mt++)
#pragma unroll
                for (int nt = 0; nt < 4; nt++)
                    MMA_TF32(acc[mt][nt], af[mt], bf[nt][0], bf[nt][1]);
        }
        if (kt + 1 < nkt) {
            uint32_t* dA = smg + (1 - cur) * 2 * GASZ;
            uint32_t* dB = dA + GASZ;
#pragma unroll
            for (int i = 0; i < 4; i++) {
                int idx = t + i * 256;
                int r = idx >> 3, c4 = idx & 7;
                uint32_t* da = &dA[r * GPITCH + c4 * 4];
                da[0] = f2tf32(ra[i].x); da[1] = f2tf32(ra[i].y);
                da[2] = f2tf32(ra[i].z); da[3] = f2tf32(ra[i].w);
                uint32_t* db = &dB[r * GPITCH + c4 * 4];
                db[0] = f2tf32(rb[i].x); db[1] = f2tf32(rb[i].y);
                db[2] = f2tf32(rb[i].z); db[3] = f2tf32(rb[i].w);
            }
        }
        __syncthreads();
    }

#pragma unroll
    for (int mt = 0; mt < 4; mt++) {
        int r = m0 + wm * 64 + mt * 16 + lr;
#pragma unroll
        for (int nt = 0; nt < 4; nt++) {
            int c = n0 + wn * 32 + nt * 8 + 2 * lc;
            float2 bv = *(const float2*)&bias[c];
            float2 o0, o1;
            o0.x = acc[mt][nt][0] + bv.x; o0.y = acc[mt][nt][1] + bv.y;
            o1.x = acc[mt][nt][2] + bv.x; o1.y = acc[mt][nt][3] + bv.y;
            *(float2*)&C[(size_t)r * N + c]       = o0;
            *(float2*)&C[(size_t)(r + 8) * N + c] = o1;
        }
    }
}

// =====================================================================
// beta[row] = 1 / (||K_row||^2 + 1e-6)
// =====================================================================
__global__ void __launch_bounds__(256) beta_kernel()
{
    int row  = blockIdx.x * 8 + (threadIdx.x >> 5);
    int lane = threadIdx.x & 31;
    const float* p = g_K + (size_t)row * ND;
    float s = 0.f;
#pragma unroll
    for (int i = 0; i < 8; i++) {
        float4 v = *(const float4*)&p[lane * 4 + i * 128];
        s += v.x * v.x + v.y * v.y + v.z * v.z + v.w * v.w;
    }
#pragma unroll
    for (int o = 16; o; o >>= 1) s += __shfl_xor_sync(0xffffffffu, s, o);
    if (lane == 0) g_beta[row] = 1.f / (s + 1e-6f);
}

// =====================================================================
// prep: per (batch, chunk) block.
// emits: A (row-major), U (g_V), and fragment-ordered pre-split
// Qf/Qfl, Ktf/Ktfl, Wf/Wfl (W negated).
// =====================================================================
#define PPAD 35
__global__ void __launch_bounds__(256) prep_kernel()
{
    __shared__ float sA[64 * PPAD];
    __shared__ float sB[64 * PPAD];
    __shared__ float T_s[64 * 64];
    __shared__ float rowtmp[64];
    __shared__ float beta_s[64];

    const int t  = threadIdx.x;
    const int bc = blockIdx.x;
    const size_t row0 = (size_t)(bc >> 6) * NL + (size_t)(bc & 63) * 64;
    const size_t fb   = (size_t)bc * 65536;   // hi frag base (uint32)
    const size_t flb  = (size_t)bc * 32768;   // lo frag base (uint32)

    if (t < 64) beta_s[t] = g_beta[row0 + t];
    __syncthreads();

    const int i0  = (t >> 4) * 4;
    const int j0  = (t & 15) * 4;
    const int lkk = t & 31, ljr = t >> 5;
    const int lane = t & 31, flr = lane >> 2, flc = lane & 3;

    float ga[4][4], qa[4][4];
#pragma unroll
    for (int a = 0; a < 4; a++)
#pragma unroll
        for (int b = 0; b < 4; b++) { ga[a][b] = 0.f; qa[a][b] = 0.f; }

    for (int k0 = 0; k0 < ND; k0 += 32) {
#pragma unroll
        for (int h = 0; h < 8; h++) {
            int j = ljr + h * 8;
            sA[j * PPAD + lkk] = g_K[(row0 + j) * ND + k0 + lkk];
            sB[j * PPAD + lkk] = g_Q[(row0 + j) * ND + k0 + lkk];
        }
        __syncthreads();

        // ---- emit Q fragments (A-operand order) ----
#pragma unroll
        for (int h = 0; h < 2; h++) {
            int idx = t + h * 256;
            int kgl = idx >> 7;
            int mg  = (idx >> 5) & 3;
            int kk  = kgl * 8 + flc;
            float a0 = sB[(mg * 16 + flr) * PPAD + kk];
            float a1 = sB[(mg * 16 + flr + 8) * PPAD + kk];
            float a2 = sB[(mg * 16 + flr) * PPAD + kk + 4];
            float a3 = sB[(mg * 16 + flr + 8) * PPAD + kk + 4];
            uint32_t h0 = f2tf32(a0), h1 = f2tf32(a1);
            uint32_t h2 = f2tf32(a2), h3 = f2tf32(a3);
            int kg = (k0 >> 3) + kgl;
            *(uint4*)&g_Qf[fb + (size_t)(kg * 4 + mg) * 128 + lane * 4] =
                make_uint4(h0, h1, h2, h3);
            uint32_t lo01 = (uint32_t)bf16bits(a0 - __uint_as_float(h0))
                          | ((uint32_t)bf16bits(a1 - __uint_as_float(h1)) << 16);
            uint32_t lo23 = (uint32_t)bf16bits(a2 - __uint_as_float(h2))
                          | ((uint32_t)bf16bits(a3 - __uint_as_float(h3)) << 16);
            *(uint2*)&g_Qfl[flb + (size_t)(kg * 4 + mg) * 64 + lane * 2] =
                make_uint2(lo01, lo23);
        }
        // ---- emit K^T fragments (B-operand order) ----
#pragma unroll
        for (int h = 0; h < 4; h++) {
            int idx = t + h * 256;
            int ngl = idx >> 8;
            int j8  = (idx >> 5) & 7;
            float b0 = sA[(j8 * 8 + flc) * PPAD + ngl * 8 + flr];
            float b1 = sA[(j8 * 8 + flc + 4) * PPAD + ngl * 8 + flr];
            uint32_t h0 = f2tf32(b0), h1 = f2tf32(b1);
            int ng = (k0 >> 3) + ngl;
            *(uint2*)&g_Ktf[fb + (size_t)(ng * 8 + j8) * 64 + lane * 2] =
                make_uint2(h0, h1);
            g_Ktfl[flb + (size_t)(ng * 8 + j8) * 32 + lane] =
                  (uint32_t)bf16bits(b0 - __uint_as_float(h0))
                | ((uint32_t)bf16bits(b1 - __uint_as_float(h1)) << 16);
        }

#pragma unroll
        for (int kk = 0; kk < 32; kk++) {
            float ki[4], kj[4], qi[4];
#pragma unroll
            for (int a = 0; a < 4; a++) {
                ki[a] = sA[(i0 + a) * PPAD + kk];
                qi[a] = sB[(i0 + a) * PPAD + kk];
                kj[a] = sA[(j0 + a) * PPAD + kk];
            }
#pragma unroll
            for (int a = 0; a < 4; a++)
#pragma unroll
                for (int b = 0; b < 4; b++) {
                    ga[a][b] += ki[a] * kj[b];
                    qa[a][b] += qi[a] * kj[b];
                }
        }
        __syncthreads();
    }

    float* Aout = g_A + (size_t)bc * 4096;
#pragma unroll
    for (int a = 0; a < 4; a++)
#pragma unroll
        for (int b = 0; b < 4; b++) {
            int i = i0 + a, j = j0 + b;
            T_s[i * 64 + j]  = (j < i) ? (-beta_s[i] * ga[a][b]) : 0.f;
            Aout[i * 64 + j] = (j <= i) ? qa[a][b] : 0.f;
        }
    __syncthreads();

    for (int i = 1; i < 64; i++) {
        if (t < i) rowtmp[t] = T_s[i * 64 + t];
        __syncthreads();
        if (t < i) {
            float s = 0.f;
            for (int j = t + 1; j < i; j++) s += rowtmp[j] * T_s[j * 64 + t];
            T_s[i * 64 + t] += s;
        }
        __syncthreads();
    }
    if (t < 64) T_s[t * 64 + t] += 1.f;
    __syncthreads();

    const int ip = (t >> 4) * 4;
    const int dp = (t & 15) * 2;
    for (int d0 = 0; d0 < ND; d0 += 32) {
#pragma unroll
        for (int h = 0; h < 8; h++) {
            int j = ljr + h * 8;
            float bj = beta_s[j];
            sA[j * PPAD + lkk] = g_K[(row0 + j) * ND + d0 + lkk] * bj;
            sB[j * PPAD + lkk] = g_V[(row0 + j) * ND + d0 + lkk] * bj;
        }
        __syncthreads();
        float wv[4][2], uv[4][2];
#pragma unroll
        for (int a = 0; a < 4; a++) { wv[a][0] = wv[a][1] = 0.f; uv[a][0] = uv[a][1] = 0.f; }
#pragma unroll
        for (int j = 0; j < 64; j++) {
            float kb0 = sA[j * PPAD + dp], kb1 = sA[j * PPAD + dp + 1];
            float vb0 = sB[j * PPAD + dp], vb1 = sB[j * PPAD + dp + 1];
#pragma unroll
            for (int a = 0; a < 4; a++) {
                float tv = T_s[(ip + a) * 64 + j];
                wv[a][0] += tv * kb0; wv[a][1] += tv * kb1;
                uv[a][0] += tv * vb0; uv[a][1] += tv * vb1;
            }
        }
#pragma unroll
        for (int a = 0; a < 4; a++) {
            size_t off = (row0 + ip + a) * ND + d0 + dp;
            *(float2*)&g_V[off] = make_float2(uv[a][0], uv[a][1]);
        }
        __syncthreads();
        // stash -W window into sA
#pragma unroll
        for (int a = 0; a < 4; a++) {
            sA[(ip + a) * PPAD + dp]     = -wv[a][0];
            sA[(ip + a) * PPAD + dp + 1] = -wv[a][1];
        }
        __syncthreads();
        // emit -W fragments (A-operand order)
#pragma unroll
        for (int h = 0; h < 2; h++) {
            int idx = t + h * 256;
            int kgl = idx >> 7;
            int mg  = (idx >> 5) & 3;
            int kk  = kgl * 8 + flc;
            float a0 = sA[(mg * 16 + flr) * PPAD + kk];
            float a1 = sA[(mg * 16 + flr + 8) * PPAD + kk];
            float a2 = sA[(mg * 16 + flr) * PPAD + kk + 4];
            float a3 = sA[(mg * 16 + flr + 8) * PPAD + kk + 4];
            uint32_t h0 = f2tf32(a0), h1 = f2tf32(a1);
            uint32_t h2 = f2tf32(a2), h3 = f2tf32(a3);
            int kg = (d0 >> 3) + kgl;
            *(uint4*)&g_Wf[fb + (size_t)(kg * 4 + mg) * 128 + lane * 4] =
                make_uint4(h0, h1, h2, h3);
            uint32_t lo01 = (uint32_t)bf16bits(a0 - __uint_as_float(h0))
                          | ((uint32_t)bf16bits(a1 - __uint_as_float(h1)) << 16);
            uint32_t lo23 = (uint32_t)bf16bits(a2 - __uint_as_float(h2))
                          | ((uint32_t)bf16bits(a3 - __uint_as_float(h3)) << 16);
            *(uint2*)&g_Wfl[flb + (size_t)(kg * 4 + mg) * 64 + lane * 2] =
                make_uint2(lo01, lo23);
        }
        __syncthreads();
    }
}

// =====================================================================
// scan (tensor, 3xTF32, fragment-ready layouts)
// grid (32 colblocks, 8 batches), 256 thr, S^T hi/lo in pair-packed smem.
// =====================================================================
#define SH_P   1032                 // Sh float pitch (%32==8)
#define SLW_P  516                  // Sl uint32 pitch (%32==4); ushort pitch 1032
#define UH_P   72                   // Uh float pitch (%32==8)
#define ULW_P  36                   // Ul uint32 pitch (%32==4); ushort pitch 72
#define OFF_SLW 132096
#define OFF_UH  198144
#define OFF_ULW 207360
#define SCAN_SMEM2 211968

__global__ void __launch_bounds__(256, 1) scan_tc()
{
    extern __shared__ char smc[];
    float*          Sh   = (float*)smc;
    uint32_t*       SlW  = (uint32_t*)(smc + OFF_SLW);
    unsigned short* Sl16 = (unsigned short*)SlW;
    float*          Uh   = (float*)(smc + OFF_UH);
    uint32_t*       UlW  = (uint32_t*)(smc + OFF_ULW);
    unsigned short* Ul16 = (unsigned short*)UlW;

    const int t    = threadIdx.x;
    const int lane = t & 31;
    const int wid  = t >> 5;
    const int lr   = lane >> 2;
    const int lc   = lane & 3;
    const int b    = blockIdx.y;
    const int cb0  = blockIdx.x * 32;

    for (int i = t; i < 32 * SH_P; i += 256) Sh[i] = 0.f;
    for (int i = t; i < 32 * SLW_P; i += 256) SlW[i] = 0u;
    __syncthreads();

    const int  mg  = wid & 3;          // phase b/c m-group (rows mg*16..+15)
    const bool isQ = (wid >= 4);
    const int  dm  = (wid & 1) * 16;   // phase d cc-half
    const int  dn  = (wid >> 1) * 256; // phase d kdim quarter

    for (int n = 0; n < 64; n++) {
        const size_t row0  = (size_t)b * NL + (size_t)n * 64;
        const size_t cbase = (size_t)b * 64 + n;

        // ---------------- phase b: u = U0 - W@S ; qs = Q@S ----------------
        float acc[4][4];
        if (!isQ) {
            const size_t rr = row0 + mg * 16 + lr;
#pragma unroll
            for (int nt = 0; nt < 4; nt++) {
                int cc = cb0 + nt * 8 + 2 * lc;
                float2 v0 = *(const float2*)&g_V[rr * ND + cc];
                float2 v1 = *(const float2*)&g_V[(rr + 8) * ND + cc];
                acc[nt][0] = v0.x; acc[nt][1] = v0.y;
                acc[nt][2] = v1.x; acc[nt][3] = v1.y;
            }
        } else {
#pragma unroll
            for (int nt = 0; nt < 4; nt++)
#pragma unroll
                for (int x = 0; x < 4; x++) acc[nt][x] = 0.f;
        }
        {
            const uint32_t* Afh = (isQ ? g_Qf  : g_Wf)  + cbase * 65536;
            const uint32_t* Afl = (isQ ? g_Qfl : g_Wfl) + cbase * 32768;
#pragma unroll 2
            for (int k8 = 0; k8 < 128; k8++) {
                uint4 ah4 = *(const uint4*)&Afh[(size_t)(k8 * 4 + mg) * 128 + lane * 4];
                uint2 al2 = *(const uint2*)&Afl[(size_t)(k8 * 4 + mg) * 64 + lane * 2];
                uint32_t ah[4] = {ah4.x, ah4.y, ah4.z, ah4.w};
                uint32_t al[4] = {al2.x << 16, al2.x & 0xFFFF0000u,
                                  al2.y << 16, al2.y & 0xFFFF0000u};
#pragma unroll
                for (int nt = 0; nt < 4; nt++) {
                    int nr = nt * 8 + lr;
                    float2 bh2 = *(const float2*)&Sh[nr * SH_P + k8 * 8 + 2 * lc];
                    uint32_t blp = SlW[nr * SLW_P + k8 * 4 + lc];
                    uint32_t bh0 = __float_as_uint(bh2.x);
                    uint32_t bh1 = __float_as_uint(bh2.y);
                    MMA_TF32(acc[nt], ah, bh0, bh1);
                    MMA_TF32(acc[nt], ah, blp << 16, blp & 0xFFFF0000u);
                    MMA_TF32(acc[nt], al, bh0, bh1);
                }
            }
        }
        // u-warps: write u^T hi/lo into pair-packed smem
        if (!isQ) {
#pragma unroll
            for (int nt = 0; nt < 4; nt++) {
#pragma unroll
                for (int x = 0; x < 4; x++) {
                    int cc = nt * 8 + 2 * lc + (x & 1);
                    int j  = mg * 16 + lr + ((x >> 1) << 3);
                    int slot = (j & ~7) + 2 * (lr & 3) + (lr >> 2);
                    float v  = acc[nt][x];
                    uint32_t hh = f2tf32(v);
                    float hf = __uint_as_float(hh);
                    Uh[cc * UH_P + slot]   = hf;
                    Ul16[cc * UH_P + slot] = bf16bits(v - hf);
                }
            }
        }
        __syncthreads();

        // ---------------- phase c (q-warps): O = A@u + qs ----------------
        if (isQ) {
            const float* Ab = g_A + cbase * 4096;
#pragma unroll 2
            for (int j8 = 0; j8 < 8; j8++) {
                float a0 = Ab[(mg * 16 + lr) * 64 + j8 * 8 + lc];
                float a1 = Ab[(mg * 16 + lr + 8) * 64 + j8 * 8 + lc];
                float a2 = Ab[(mg * 16 + lr) * 64 + j8 * 8 + lc + 4];
                float a3 = Ab[(mg * 16 + lr + 8) * 64 + j8 * 8 + lc + 4];
                uint32_t ah[4], al[4];
                tsplit(a0, ah[0], al[0]); tsplit(a1, ah[1], al[1]);
                tsplit(a2, ah[2], al[2]); tsplit(a3, ah[3], al[3]);
#pragma unroll
                for (int nt = 0; nt < 4; nt++) {
                    int nr = nt * 8 + lr;
                    float2 bh2 = *(const float2*)&Uh[nr * UH_P + j8 * 8 + 2 * lc];
                    uint32_t blp = UlW[nr * ULW_P + j8 * 4 + lc];
                    uint32_t bh0 = __float_as_uint(bh2.x);
                    uint32_t bh1 = __float_as_uint(bh2.y);
                    MMA_TF32(acc[nt], ah, bh0, bh1);
                    MMA_TF32(acc[nt], ah, blp << 16, blp & 0xFFFF0000u);
                    MMA_TF32(acc[nt], al, bh0, bh1);
                }
            }
            const size_t rr = row0 + mg * 16 + lr;
#pragma unroll
            for (int nt = 0; nt < 4; nt++) {
                int cc = cb0 + nt * 8 + 2 * lc;
                *(float2*)&g_O[rr * ND + cc]       = make_float2(acc[nt][0], acc[nt][1]);
                *(float2*)&g_O[(rr + 8) * ND + cc] = make_float2(acc[nt][2], acc[nt][3]);
            }
        }

        // ---------------- phase d: S += K^T @ u (as dS^T = u^T@K^T) -------
        {
            const uint32_t* Kfh = g_Ktf  + cbase * 65536;
            const uint32_t* Kfl = g_Ktfl + cbase * 32768;
            for (int sb = 0; sb < 4; sb++) {
                const int kb0 = dn + sb * 64;
                const int ng0 = kb0 >> 3;
                float dacc[8][4];
#pragma unroll
                for (int i = 0; i < 8; i++)
#pragma unroll
                    for (int x = 0; x < 4; x++) dacc[i][x] = 0.f;
#pragma unroll 2
                for (int j8 = 0; j8 < 8; j8++) {
                    float2 h0 = *(const float2*)&Uh[(dm + lr) * UH_P + j8 * 8 + 2 * lc];
                    float2 h8 = *(const float2*)&Uh[(dm + lr + 8) * UH_P + j8 * 8 + 2 * lc];
                    uint32_t l0 = UlW[(dm + lr) * ULW_P + j8 * 4 + lc];
                    uint32_t l8 = UlW[(dm + lr + 8) * ULW_P + j8 * 4 + lc];
                    uint32_t ah[4] = {__float_as_uint(h0.x), __float_as_uint(h8.x),
                                      __float_as_uint(h0.y), __float_as_uint(h8.y)};
                    uint32_t al[4] = {l0 << 16, l8 << 16,
                                      l0 & 0xFFFF0000u, l8 & 0xFFFF0000u};
#pragma unroll
                    for (int nt = 0; nt < 8; nt++) {
                        size_t fo = (size_t)((ng0 + nt) * 8 + j8) * 32 + lane;
                        uint2 bh = *(const uint2*)&Kfh[fo * 2];
                        uint32_t bl = Kfl[fo];
                        MMA_TF32(dacc[nt], ah, bh.x, bh.y);
                        MMA_TF32(dacc[nt], ah, bl << 16, bl & 0xFFFF0000u);
                        MMA_TF32(dacc[nt], al, bh.x, bh.y);
                    }
                }
                // update S^T hi/lo (permuted pair-packed indices)
#pragma unroll
                for (int nt = 0; nt < 8; nt++) {
                    int kxb = kb0 + nt * 8 + 2 * lc;
#pragma unroll
                    for (int x = 0; x < 4; x++) {
                        int cc  = dm + lr + ((x >> 1) << 3);
                        int kx  = kxb + (x & 1);
                        int off = kx & 7;
                        int slot = (kx & ~7) + 2 * (off & 3) + (off >> 2);
                        int i = cc * SH_P + slot;
                        float s = Sh[i] + bf16f(Sl16[i]) + dacc[nt][x];
                        uint32_t hh = f2tf32(s);
                        float hf = __uint_as_float(hh);
                        Sh[i]   = hf;
                        Sl16[i] = bf16bits(s - hf);
                    }
                }
            }
        }
        __syncthreads();
    }
}

// =====================================================================
extern "C" void kernel_launch(void* const* d_in, const int* in_sizes, int n_in,
                              void* d_out, int out_size)
{
    int base = 1;
    if (n_in >= 10 && in_sizes[1] == 1) base = 2;
    const float* X    = (const float*)d_in[0];
    const float* Wq_w = (const float*)d_in[base + 0];
    const float* Wq_b = (const float*)d_in[base + 1];
    const float* Wk_w = (const float*)d_in[base + 2];
    const float* Wk_b = (const float*)d_in[base + 3];
    const float* Wv_w = (const float*)d_in[base + 4];
    const float* Wv_b = (const float*)d_in[base + 5];
    const float* Wo_w = (const float*)d_in[base + 6];
    const float* Wo_b = (const float*)d_in[base + 7];
    float* out = (float*)d_out;

    float *pQ, *pK, *pV, *pO;
    cudaGetSymbolAddress((void**)&pQ, g_Q);
    cudaGetSymbolAddress((void**)&pK, g_K);
    cudaGetSymbolAddress((void**)&pV, g_V);
    cudaGetSymbolAddress((void**)&pO, g_O);

    cudaFuncSetAttribute(gemm_mma, cudaFuncAttributeMaxDynamicSharedMemorySize, GSMEM);
    dim3 gg(ND / 128, NROWS / 128);
    gemm_mma<<<gg, 256, GSMEM>>>(X, Wq_w, Wq_b, pQ, NROWS, ND, ND);
    gemm_mma<<<gg, 256, GSMEM>>>(X, Wk_w, Wk_b, pK, NROWS, ND, ND);
    gemm_mma<<<gg, 256, GSMEM>>>(X, Wv_w, Wv_b, pV, NROWS, ND, ND);
    beta_kernel<<<NROWS / 8, 256>>>();
    prep_kernel<<<NB * 64, 256>>>();
    cudaFuncSetAttribute(scan_tc, cudaFuncAttributeMaxDynamicSharedMemorySize, SCAN_SMEM2);
    scan_tc<<<dim3(32, NB), 256, SCAN_SMEM2>>>();
    gemm_mma<<<gg, 256, GSMEM>>>(pO, Wo_w, Wo_b, out, NROWS, ND, ND);
}

// round 7
// speedup vs baseline: 1.3482x; 1.3482x over previous
#include <cuda_runtime.h>
#include <cuda_bf16.h>
#include <cstdint>
#include <cstddef>

#define NB 8
#define NL 4096
#define ND 1024
#define NROWS (NB*NL)   // 32768

// ---- scratch (device globals; no allocation allowed) ----
__device__ float    g_Q[(size_t)NROWS * ND];
__device__ float    g_K[(size_t)NROWS * ND];
__device__ float    g_V[(size_t)NROWS * ND];      // becomes U (=T@Vb) in place
__device__ float    g_O[(size_t)NROWS * ND];
__device__ float    g_beta[NROWS];
__device__ float    g_A[(size_t)NB * 64 * 64 * 64];
// bf16 2-plane fragment-ordered operands for the scan
__device__ uint32_t g_Qfh [(size_t)NROWS * ND / 2];
__device__ uint32_t g_Qfm [(size_t)NROWS * ND / 2];
__device__ uint32_t g_Wfh [(size_t)NROWS * ND / 2];   // -W
__device__ uint32_t g_Wfm [(size_t)NROWS * ND / 2];
__device__ uint32_t g_Ktfh[(size_t)NROWS * ND / 2];   // K (B-frag order, j-packed)
__device__ uint32_t g_Ktfm[(size_t)NROWS * ND / 2];

__device__ __forceinline__ uint32_t f2tf32(float x) {
    uint32_t r;
    asm("cvt.rna.tf32.f32 %0, %1;" : "=r"(r) : "f"(x));
    return r;
}
__device__ __forceinline__ unsigned short bf16bits(float x) {
    return __bfloat16_as_ushort(__float2bfloat16(x));
}
__device__ __forceinline__ float bf16f(unsigned short u) {
    return __uint_as_float(((uint32_t)u) << 16);
}
// split two floats into packed bf16x2 hi and mid planes
__device__ __forceinline__ void packsplit(float a, float b, uint32_t& h, uint32_t& m) {
    unsigned short h0 = bf16bits(a), h1 = bf16bits(b);
    unsigned short m0 = bf16bits(a - bf16f(h0)), m1 = bf16bits(b - bf16f(h1));
    h = (uint32_t)h0 | ((uint32_t)h1 << 16);
    m = (uint32_t)m0 | ((uint32_t)m1 << 16);
}

#define MMA_TF32(d, a, b0, b1) \
    asm volatile("mma.sync.aligned.m16n8k8.row.col.f32.tf32.tf32.f32 " \
        "{%0,%1,%2,%3}, {%4,%5,%6,%7}, {%8,%9}, {%0,%1,%2,%3};" \
        : "+f"((d)[0]), "+f"((d)[1]), "+f"((d)[2]), "+f"((d)[3]) \
        : "r"((a)[0]), "r"((a)[1]), "r"((a)[2]), "r"((a)[3]), "r"(b0), "r"(b1))

#define MMA_BF16(d, a, b0, b1) \
    asm volatile("mma.sync.aligned.m16n8k16.row.col.f32.bf16.bf16.f32 " \
        "{%0,%1,%2,%3}, {%4,%5,%6,%7}, {%8,%9}, {%0,%1,%2,%3};" \
        : "+f"((d)[0]), "+f"((d)[1]), "+f"((d)[2]), "+f"((d)[3]) \
        : "r"((a)[0]), "r"((a)[1]), "r"((a)[2]), "r"((a)[3]), "r"(b0), "r"(b1))

// =====================================================================
// tf32 mma.sync GEMM: C(MxN) = A(MxK) @ W(NxK)^T + bias(N)
// =====================================================================
#define GPITCH 36
#define GASZ   (128 * GPITCH)
#define GSMEM  (4 * GASZ * 4)

__global__ void __launch_bounds__(256, 1) gemm_mma(
    const float* __restrict__ A, const float* __restrict__ Wm,
    const float* __restrict__ bias, float* __restrict__ C,
    int M, int N, int K)
{
    extern __shared__ uint32_t smg[];
    const int t    = threadIdx.x;
    const int wid  = t >> 5;
    const int lane = t & 31;
    const int wm   = wid & 1;
    const int wn   = wid >> 1;
    const int m0   = blockIdx.y * 128;
    const int n0   = blockIdx.x * 128;
    const int lr   = lane >> 2;
    const int lc   = lane & 3;

    const float* Ap = A  + (size_t)m0 * K;
    const float* Bp = Wm + (size_t)n0 * K;

    float acc[4][4][4];
#pragma unroll
    for (int i = 0; i < 4; i++)
#pragma unroll
        for (int j = 0; j < 4; j++)
#pragma unroll
            for (int x = 0; x < 4; x++) acc[i][j][x] = 0.f;

#pragma unroll
    for (int i = 0; i < 4; i++) {
        int idx = t + i * 256;
        int r = idx >> 3, c4 = idx & 7;
        float4 va = *(const float4*)(Ap + (size_t)r * K + c4 * 4);
        uint32_t* dst = &smg[r * GPITCH + c4 * 4];
        dst[0] = f2tf32(va.x); dst[1] = f2tf32(va.y);
        dst[2] = f2tf32(va.z); dst[3] = f2tf32(va.w);
        float4 vb = *(const float4*)(Bp + (size_t)r * K + c4 * 4);
        uint32_t* dstb = &smg[GASZ + r * GPITCH + c4 * 4];
        dstb[0] = f2tf32(vb.x); dstb[1] = f2tf32(vb.y);
        dstb[2] = f2tf32(vb.z); dstb[3] = f2tf32(vb.w);
    }
    __syncthreads();

    const int nkt = K >> 5;
    for (int kt = 0; kt < nkt; kt++) {
        const int cur = kt & 1;
        float4 ra[4], rb[4];
        if (kt + 1 < nkt) {
            const int ko = (kt + 1) * 32;
#pragma unroll
            for (int i = 0; i < 4; i++) {
                int idx = t + i * 256;
                int r = idx >> 3, c4 = idx & 7;
                ra[i] = *(const float4*)(Ap + (size_t)r * K + ko + c4 * 4);
                rb[i] = *(const float4*)(Bp + (size_t)r * K + ko + c4 * 4);
            }
        }
        const uint32_t* As = smg + cur * 2 * GASZ;
        const uint32_t* Bs = As + GASZ;
#pragma unroll
        for (int k8 = 0; k8 < 4; k8++) {
            const int kb = k8 * 8 + lc;
            uint32_t af[4][4], bf[4][2];
#pragma unroll
            for (int mt = 0; mt < 4; mt++) {
                int r = wm * 64 + mt * 16 + lr;
                af[mt][0] = As[r * GPITCH + kb];
                af[mt][1] = As[(r + 8) * GPITCH + kb];
                af[mt][2] = As[r * GPITCH + kb + 4];
                af[mt][3] = As[(r + 8) * GPITCH + kb + 4];
            }
#pragma unroll
            for (int nt = 0; nt < 4; nt++) {
                int n = wn * 32 + nt * 8 + lr;
                bf[nt][0] = Bs[n * GPITCH + kb];
                bf[nt][1] = Bs[n * GPITCH + kb + 4];
            }
#pragma unroll
            for (int mt = 0; mt < 4; mt++)
#pragma unroll
                for (int nt = 0; nt < 4; nt++)
                    MMA_TF32(acc[mt][nt], af[mt], bf[nt][0], bf[nt][1]);
        }
        if (kt + 1 < nkt) {
            uint32_t* dA = smg + (1 - cur) * 2 * GASZ;
            uint32_t* dB = dA + GASZ;
#pragma unroll
            for (int i = 0; i < 4; i++) {
                int idx = t + i * 256;
                int r = idx >> 3, c4 = idx & 7;
                uint32_t* da = &dA[r * GPITCH + c4 * 4];
                da[0] = f2tf32(ra[i].x); da[1] = f2tf32(ra[i].y);
                da[2] = f2tf32(ra[i].z); da[3] = f2tf32(ra[i].w);
                uint32_t* db = &dB[r * GPITCH + c4 * 4];
                db[0] = f2tf32(rb[i].x); db[1] = f2tf32(rb[i].y);
                db[2] = f2tf32(rb[i].z); db[3] = f2tf32(rb[i].w);
            }
        }
        __syncthreads();
    }

#pragma unroll
    for (int mt = 0; mt < 4; mt++) {
        int r = m0 + wm * 64 + mt * 16 + lr;
#pragma unroll
        for (int nt = 0; nt < 4; nt++) {
            int c = n0 + wn * 32 + nt * 8 + 2 * lc;
            float2 bv = *(const float2*)&bias[c];
            float2 o0, o1;
            o0.x = acc[mt][nt][0] + bv.x; o0.y = acc[mt][nt][1] + bv.y;
            o1.x = acc[mt][nt][2] + bv.x; o1.y = acc[mt][nt][3] + bv.y;
            *(float2*)&C[(size_t)r * N + c]       = o0;
            *(float2*)&C[(size_t)(r + 8) * N + c] = o1;
        }
    }
}

// =====================================================================
// beta[row] = 1 / (||K_row||^2 + 1e-6)
// =====================================================================
__global__ void __launch_bounds__(256) beta_kernel()
{
    int row  = blockIdx.x * 8 + (threadIdx.x >> 5);
    int lane = threadIdx.x & 31;
    const float* p = g_K + (size_t)row * ND;
    float s = 0.f;
#pragma unroll
    for (int i = 0; i < 8; i++) {
        float4 v = *(const float4*)&p[lane * 4 + i * 128];
        s += v.x * v.x + v.y * v.y + v.z * v.z + v.w * v.w;
    }
#pragma unroll
    for (int o = 16; o; o >>= 1) s += __shfl_xor_sync(0xffffffffu, s, o);
    if (lane == 0) g_beta[row] = 1.f / (s + 1e-6f);
}

// =====================================================================
// prep: per (batch, chunk) block.
// emits: A (row-major fp32), U (g_V), and bf16 2-plane fragments:
// Qfh/Qfm, Wfh/Wfm (negated), Ktfh/Ktfm.
// =====================================================================
#define PPAD 35
__global__ void __launch_bounds__(256) prep_kernel()
{
    __shared__ float sA[64 * PPAD];
    __shared__ float sB[64 * PPAD];
    __shared__ float T_s[64 * 64];
    __shared__ float rowtmp[64];
    __shared__ float beta_s[64];

    const int t  = threadIdx.x;
    const int bc = blockIdx.x;
    const size_t row0 = (size_t)(bc >> 6) * NL + (size_t)(bc & 63) * 64;
    const size_t fb   = (size_t)bc * 32768;   // frag plane base (uint32)

    if (t < 64) beta_s[t] = g_beta[row0 + t];
    __syncthreads();

    const int i0  = (t >> 4) * 4;
    const int j0  = (t & 15) * 4;
    const int lkk = t & 31, ljr = t >> 5;
    const int lane = t & 31, flr = lane >> 2, flc = lane & 3;
    const int grp  = t >> 5;

    float ga[4][4], qa[4][4];
#pragma unroll
    for (int a = 0; a < 4; a++)
#pragma unroll
        for (int b = 0; b < 4; b++) { ga[a][b] = 0.f; qa[a][b] = 0.f; }

    for (int k0 = 0; k0 < ND; k0 += 32) {
#pragma unroll
        for (int h = 0; h < 8; h++) {
            int j = ljr + h * 8;
            sA[j * PPAD + lkk] = g_K[(row0 + j) * ND + k0 + lkk];
            sB[j * PPAD + lkk] = g_Q[(row0 + j) * ND + k0 + lkk];
        }
        __syncthreads();

        // ---- emit Q fragments (A-operand, 2 k16 x 4 mg groups) ----
        {
            int k16l = grp >> 2, mg = grp & 3;
            int r0 = mg * 16 + flr;
            int kb = k16l * 16 + 2 * flc;
            uint32_t ah[4], am[4];
            packsplit(sB[r0 * PPAD + kb],           sB[r0 * PPAD + kb + 1],           ah[0], am[0]);
            packsplit(sB[(r0 + 8) * PPAD + kb],     sB[(r0 + 8) * PPAD + kb + 1],     ah[1], am[1]);
            packsplit(sB[r0 * PPAD + kb + 8],       sB[r0 * PPAD + kb + 9],           ah[2], am[2]);
            packsplit(sB[(r0 + 8) * PPAD + kb + 8], sB[(r0 + 8) * PPAD + kb + 9],     ah[3], am[3]);
            size_t o = fb + (size_t)(((k0 >> 4) + k16l) * 4 + mg) * 128 + lane * 4;
            *(uint4*)&g_Qfh[o] = make_uint4(ah[0], ah[1], ah[2], ah[3]);
            *(uint4*)&g_Qfm[o] = make_uint4(am[0], am[1], am[2], am[3]);
        }
        // ---- emit K fragments (B-operand, 4 ngl x 4 j16 groups, 2 passes) ----
#pragma unroll
        for (int h = 0; h < 2; h++) {
            int g2 = grp + h * 8;
            int ngl = g2 & 3, j16 = g2 >> 2;
            int nn = ngl * 8 + flr;
            int jb = j16 * 16 + 2 * flc;
            uint32_t bh0, bm0, bh1, bm1;
            packsplit(sA[jb * PPAD + nn],       sA[(jb + 1) * PPAD + nn], bh0, bm0);
            packsplit(sA[(jb + 8) * PPAD + nn], sA[(jb + 9) * PPAD + nn], bh1, bm1);
            size_t o = fb + (size_t)(((k0 >> 3) + ngl) * 4 + j16) * 64 + lane * 2;
            *(uint2*)&g_Ktfh[o] = make_uint2(bh0, bh1);
            *(uint2*)&g_Ktfm[o] = make_uint2(bm0, bm1);
        }

#pragma unroll
        for (int kk = 0; kk < 32; kk++) {
            float ki[4], kj[4], qi[4];
#pragma unroll
            for (int a = 0; a < 4; a++) {
                ki[a] = sA[(i0 + a) * PPAD + kk];
                qi[a] = sB[(i0 + a) * PPAD + kk];
                kj[a] = sA[(j0 + a) * PPAD + kk];
            }
#pragma unroll
            for (int a = 0; a < 4; a++)
#pragma unroll
                for (int b = 0; b < 4; b++) {
                    ga[a][b] += ki[a] * kj[b];
                    qa[a][b] += qi[a] * kj[b];
                }
        }
        __syncthreads();
    }

    float* Aout = g_A + (size_t)bc * 4096;
#pragma unroll
    for (int a = 0; a < 4; a++)
#pragma unroll
        for (int b = 0; b < 4; b++) {
            int i = i0 + a, j = j0 + b;
            T_s[i * 64 + j]  = (j < i) ? (-beta_s[i] * ga[a][b]) : 0.f;
            Aout[i * 64 + j] = (j <= i) ? qa[a][b] : 0.f;
        }
    __syncthreads();

    for (int i = 1; i < 64; i++) {
        if (t < i) rowtmp[t] = T_s[i * 64 + t];
        __syncthreads();
        if (t < i) {
            float s = 0.f;
            for (int j = t + 1; j < i; j++) s += rowtmp[j] * T_s[j * 64 + t];
            T_s[i * 64 + t] += s;
        }
        __syncthreads();
    }
    if (t < 64) T_s[t * 64 + t] += 1.f;
    __syncthreads();

    const int ip = (t >> 4) * 4;
    const int dp = (t & 15) * 2;
    for (int d0 = 0; d0 < ND; d0 += 32) {
#pragma unroll
        for (int h = 0; h < 8; h++) {
            int j = ljr + h * 8;
            float bj = beta_s[j];
            sA[j * PPAD + lkk] = g_K[(row0 + j) * ND + d0 + lkk] * bj;
            sB[j * PPAD + lkk] = g_V[(row0 + j) * ND + d0 + lkk] * bj;
        }
        __syncthreads();
        float wv[4][2], uv[4][2];
#pragma unroll
        for (int a = 0; a < 4; a++) { wv[a][0] = wv[a][1] = 0.f; uv[a][0] = uv[a][1] = 0.f; }
#pragma unroll
        for (int j = 0; j < 64; j++) {
            float kb0 = sA[j * PPAD + dp], kb1 = sA[j * PPAD + dp + 1];
            float vb0 = sB[j * PPAD + dp], vb1 = sB[j * PPAD + dp + 1];
#pragma unroll
            for (int a = 0; a < 4; a++) {
                float tv = T_s[(ip + a) * 64 + j];
                wv[a][0] += tv * kb0; wv[a][1] += tv * kb1;
                uv[a][0] += tv * vb0; uv[a][1] += tv * vb1;
            }
        }
#pragma unroll
        for (int a = 0; a < 4; a++) {
            size_t off = (row0 + ip + a) * ND + d0 + dp;
            *(float2*)&g_V[off] = make_float2(uv[a][0], uv[a][1]);
        }
        __syncthreads();
        // stash -W window into sA
#pragma unroll
        for (int a = 0; a < 4; a++) {
            sA[(ip + a) * PPAD + dp]     = -wv[a][0];
            sA[(ip + a) * PPAD + dp + 1] = -wv[a][1];
        }
        __syncthreads();
        // emit -W fragments (A-operand)
        {
            int k16l = grp >> 2, mg = grp & 3;
            int r0 = mg * 16 + flr;
            int kb = k16l * 16 + 2 * flc;
            uint32_t ah[4], am[4];
            packsplit(sA[r0 * PPAD + kb],           sA[r0 * PPAD + kb + 1],       ah[0], am[0]);
            packsplit(sA[(r0 + 8) * PPAD + kb],     sA[(r0 + 8) * PPAD + kb + 1], ah[1], am[1]);
            packsplit(sA[r0 * PPAD + kb + 8],       sA[r0 * PPAD + kb + 9],       ah[2], am[2]);
            packsplit(sA[(r0 + 8) * PPAD + kb + 8], sA[(r0 + 8) * PPAD + kb + 9], ah[3], am[3]);
            size_t o = fb + (size_t)(((d0 >> 4) + k16l) * 4 + mg) * 128 + lane * 4;
            *(uint4*)&g_Wfh[o] = make_uint4(ah[0], ah[1], ah[2], ah[3]);
            *(uint4*)&g_Wfm[o] = make_uint4(am[0], am[1], am[2], am[3]);
        }
        __syncthreads();
    }
}

// =====================================================================
// scan (tensor, bf16x3 via m16n8k16): grid (32 colblocks, 8 batches).
// S^T in smem as 3 packed-bf16x2 planes (hi/mid/lo), u^T as 2 planes.
// =====================================================================
#define SP 516                  // S plane pitch in uint32 (mod 32 == 4)
#define UP 36                   // u plane pitch in uint32 (mod 32 == 4)
#define OFF_SM (32 * SP * 4)
#define OFF_SL (2 * 32 * SP * 4)
#define OFF_UH (3 * 32 * SP * 4)
#define OFF_UM (OFF_UH + 32 * UP * 4)
#define SCAN_SMEM3 (OFF_UM + 32 * UP * 4)   // 207360

__global__ void __launch_bounds__(256, 1) scan_tc()
{
    extern __shared__ char smc[];
    uint32_t* ShP = (uint32_t*)smc;
    uint32_t* SmP = (uint32_t*)(smc + OFF_SM);
    uint32_t* SlP = (uint32_t*)(smc + OFF_SL);
    uint32_t* UhP = (uint32_t*)(smc + OFF_UH);
    uint32_t* UmP = (uint32_t*)(smc + OFF_UM);
    unsigned short* Uh16 = (unsigned short*)UhP;
    unsigned short* Um16 = (unsigned short*)UmP;

    const int t    = threadIdx.x;
    const int lane = t & 31;
    const int wid  = t >> 5;
    const int lr   = lane >> 2;
    const int lc   = lane & 3;
    const int b    = blockIdx.y;
    const int cb0  = blockIdx.x * 32;

    for (int i = t; i < 32 * SP; i += 256) { ShP[i] = 0u; SmP[i] = 0u; SlP[i] = 0u; }
    __syncthreads();

    const int  mg  = wid & 3;
    const bool isQ = (wid >= 4);
    const int  dm  = (wid & 1) * 16;
    const int  dn  = (wid >> 1) * 256;

    for (int n = 0; n < 64; n++) {
        const size_t row0  = (size_t)b * NL + (size_t)n * 64;
        const size_t cbase = (size_t)b * 64 + n;

        // ---------------- phase b: u = U0 - W@S ; qs = Q@S ----------------
        float acc[4][4];
        if (!isQ) {
            const size_t rr = row0 + mg * 16 + lr;
#pragma unroll
            for (int nt = 0; nt < 4; nt++) {
                int cc = cb0 + nt * 8 + 2 * lc;
                float2 v0 = *(const float2*)&g_V[rr * ND + cc];
                float2 v1 = *(const float2*)&g_V[(rr + 8) * ND + cc];
                acc[nt][0] = v0.x; acc[nt][1] = v0.y;
                acc[nt][2] = v1.x; acc[nt][3] = v1.y;
            }
        } else {
#pragma unroll
            for (int nt = 0; nt < 4; nt++)
#pragma unroll
                for (int x = 0; x < 4; x++) acc[nt][x] = 0.f;
        }
        {
            const uint32_t* Afh = (isQ ? g_Qfh : g_Wfh) + cbase * 32768;
            const uint32_t* Afm = (isQ ? g_Qfm : g_Wfm) + cbase * 32768;
#pragma unroll 2
            for (int k16 = 0; k16 < 64; k16++) {
                uint4 h4 = *(const uint4*)&Afh[(size_t)(k16 * 4 + mg) * 128 + lane * 4];
                uint4 m4 = *(const uint4*)&Afm[(size_t)(k16 * 4 + mg) * 128 + lane * 4];
                uint32_t ah[4] = {h4.x, h4.y, h4.z, h4.w};
                uint32_t am[4] = {m4.x, m4.y, m4.z, m4.w};
#pragma unroll
                for (int nt = 0; nt < 4; nt++) {
                    int base = (nt * 8 + lr) * SP + k16 * 8 + lc;
                    uint32_t bh0 = ShP[base], bh1 = ShP[base + 4];
                    uint32_t bm0 = SmP[base], bm1 = SmP[base + 4];
                    MMA_BF16(acc[nt], ah, bh0, bh1);
                    MMA_BF16(acc[nt], ah, bm0, bm1);
                    MMA_BF16(acc[nt], am, bh0, bh1);
                }
            }
        }
        // u-warps: write u^T hi/mid planes (packed along j via ushort stores)
        if (!isQ) {
#pragma unroll
            for (int nt = 0; nt < 4; nt++) {
#pragma unroll
                for (int x = 0; x < 4; x++) {
                    int cc = nt * 8 + 2 * lc + (x & 1);
                    int j  = mg * 16 + lr + ((x >> 1) << 3);
                    float v = acc[nt][x];
                    unsigned short h = bf16bits(v);
                    Uh16[cc * 72 + j] = h;
                    Um16[cc * 72 + j] = bf16bits(v - bf16f(h));
                }
            }
        }
        __syncthreads();

        // ---------------- phase c (q-warps): O = A@u + qs ----------------
        if (isQ) {
            const float* Ab = g_A + cbase * 4096;
#pragma unroll
            for (int j16 = 0; j16 < 4; j16++) {
                const float* ar0 = &Ab[(mg * 16 + lr) * 64 + j16 * 16 + 2 * lc];
                const float* ar1 = ar0 + 8 * 64;
                float2 p0 = *(const float2*)ar0;
                float2 p1 = *(const float2*)ar1;
                float2 p2 = *(const float2*)(ar0 + 8);
                float2 p3 = *(const float2*)(ar1 + 8);
                uint32_t ah[4], am[4];
                packsplit(p0.x, p0.y, ah[0], am[0]);
                packsplit(p1.x, p1.y, ah[1], am[1]);
                packsplit(p2.x, p2.y, ah[2], am[2]);
                packsplit(p3.x, p3.y, ah[3], am[3]);
#pragma unroll
                for (int nt = 0; nt < 4; nt++) {
                    int base = (nt * 8 + lr) * UP + j16 * 8 + lc;
                    uint32_t bh0 = UhP[base], bh1 = UhP[base + 4];
                    uint32_t bm0 = UmP[base], bm1 = UmP[base + 4];
                    MMA_BF16(acc[nt], ah, bh0, bh1);
                    MMA_BF16(acc[nt], ah, bm0, bm1);
                    MMA_BF16(acc[nt], am, bh0, bh1);
                }
            }
            const size_t rr = row0 + mg * 16 + lr;
#pragma unroll
            for (int nt = 0; nt < 4; nt++) {
                int cc = cb0 + nt * 8 + 2 * lc;
                *(float2*)&g_O[rr * ND + cc]       = make_float2(acc[nt][0], acc[nt][1]);
                *(float2*)&g_O[(rr + 8) * ND + cc] = make_float2(acc[nt][2], acc[nt][3]);
            }
        }

        // ------- phase d: S += K^T@u  (computed as dS^T = u^T @ K) --------
        {
            const uint32_t* Kfh = g_Ktfh + cbase * 32768;
            const uint32_t* Kfm = g_Ktfm + cbase * 32768;
            const int ng0 = dn >> 3;
#pragma unroll 2
            for (int ng = 0; ng < 32; ng++) {
                float dacc[4] = {0.f, 0.f, 0.f, 0.f};
#pragma unroll
                for (int j16 = 0; j16 < 4; j16++) {
                    int b0 = (dm + lr) * UP + j16 * 8 + lc;
                    int b1 = (dm + lr + 8) * UP + j16 * 8 + lc;
                    uint32_t ah[4] = {UhP[b0], UhP[b1], UhP[b0 + 4], UhP[b1 + 4]};
                    uint32_t am[4] = {UmP[b0], UmP[b1], UmP[b0 + 4], UmP[b1 + 4]};
                    size_t fo = (size_t)((ng0 + ng) * 4 + j16) * 64 + lane * 2;
                    uint2 kh = *(const uint2*)&Kfh[fo];
                    uint2 km = *(const uint2*)&Kfm[fo];
                    MMA_BF16(dacc, ah, kh.x, kh.y);
                    MMA_BF16(dacc, ah, km.x, km.y);
                    MMA_BF16(dacc, am, kh.x, kh.y);
                }
                // update S^T planes (both k-elements live in one packed word)
#pragma unroll
                for (int half = 0; half < 2; half++) {
                    int cc = dm + lr + half * 8;
                    int widx = cc * SP + (dn >> 1) + ng * 4 + lc;
                    uint32_t wh = ShP[widx], wm = SmP[widx], wl = SlP[widx];
                    float s0 = bf16f((unsigned short)(wh & 0xFFFF))
                             + bf16f((unsigned short)(wm & 0xFFFF))
                             + bf16f((unsigned short)(wl & 0xFFFF)) + dacc[half * 2];
                    float s1 = bf16f((unsigned short)(wh >> 16))
                             + bf16f((unsigned short)(wm >> 16))
                             + bf16f((unsigned short)(wl >> 16)) + dacc[half * 2 + 1];
                    unsigned short h0 = bf16bits(s0); float r0 = s0 - bf16f(h0);
                    unsigned short m0 = bf16bits(r0);
                    unsigned short l0 = bf16bits(r0 - bf16f(m0));
                    unsigned short h1 = bf16bits(s1); float r1 = s1 - bf16f(h1);
                    unsigned short m1 = bf16bits(r1);
                    unsigned short l1 = bf16bits(r1 - bf16f(m1));
                    ShP[widx] = (uint32_t)h0 | ((uint32_t)h1 << 16);
                    SmP[widx] = (uint32_t)m0 | ((uint32_t)m1 << 16);
                    SlP[widx] = (uint32_t)l0 | ((uint32_t)l1 << 16);
                }
            }
        }
        __syncthreads();
    }
}

// =====================================================================
extern "C" void kernel_launch(void* const* d_in, const int* in_sizes, int n_in,
                              void* d_out, int out_size)
{
    int base = 1;
    if (n_in >= 10 && in_sizes[1] == 1) base = 2;
    const float* X    = (const float*)d_in[0];
    const float* Wq_w = (const float*)d_in[base + 0];
    const float* Wq_b = (const float*)d_in[base + 1];
    const float* Wk_w = (const float*)d_in[base + 2];
    const float* Wk_b = (const float*)d_in[base + 3];
    const float* Wv_w = (const float*)d_in[base + 4];
    const float* Wv_b = (const float*)d_in[base + 5];
    const float* Wo_w = (const float*)d_in[base + 6];
    const float* Wo_b = (const float*)d_in[base + 7];
    float* out = (float*)d_out;

    float *pQ, *pK, *pV, *pO;
    cudaGetSymbolAddress((void**)&pQ, g_Q);
    cudaGetSymbolAddress((void**)&pK, g_K);
    cudaGetSymbolAddress((void**)&pV, g_V);
    cudaGetSymbolAddress((void**)&pO, g_O);

    cudaFuncSetAttribute(gemm_mma, cudaFuncAttributeMaxDynamicSharedMemorySize, GSMEM);
    dim3 gg(ND / 128, NROWS / 128);
    gemm_mma<<<gg, 256, GSMEM>>>(X, Wq_w, Wq_b, pQ, NROWS, ND, ND);
    gemm_mma<<<gg, 256, GSMEM>>>(X, Wk_w, Wk_b, pK, NROWS, ND, ND);
    gemm_mma<<<gg, 256, GSMEM>>>(X, Wv_w, Wv_b, pV, NROWS, ND, ND);
    beta_kernel<<<NROWS / 8, 256>>>();
    prep_kernel<<<NB * 64, 256>>>();
    cudaFuncSetAttribute(scan_tc, cudaFuncAttributeMaxDynamicSharedMemorySize, SCAN_SMEM3);
    scan_tc<<<dim3(32, NB), 256, SCAN_SMEM3>>>();
    gemm_mma<<<gg, 256, GSMEM>>>(pO, Wo_w, Wo_b, out, NROWS, ND, ND);
}

// round 9
// speedup vs baseline: 1.6106x; 1.1947x over previous
#include <cuda_runtime.h>
#include <cuda_bf16.h>
#include <cstdint>
#include <cstddef>

#define NB 8
#define NL 4096
#define ND 1024
#define NROWS (NB*NL)   // 32768

// ---- scratch (device globals; no allocation allowed) ----
__device__ float    g_Q[(size_t)NROWS * ND];
__device__ float    g_K[(size_t)NROWS * ND];
__device__ float    g_V[(size_t)NROWS * ND];      // becomes U (=T@Vb) in place
__device__ float    g_O[(size_t)NROWS * ND];
__device__ float    g_beta[NROWS];
__device__ float    g_A[(size_t)NB * 64 * 64 * 64];
// bf16 2-plane fragment-ordered operands for the scan
__device__ uint32_t g_Qfh [(size_t)NROWS * ND / 2];
__device__ uint32_t g_Qfm [(size_t)NROWS * ND / 2];
__device__ uint32_t g_Wfh [(size_t)NROWS * ND / 2];   // -W
__device__ uint32_t g_Wfm [(size_t)NROWS * ND / 2];
__device__ uint32_t g_Ktfh[(size_t)NROWS * ND / 2];   // K (B-frag order, j-packed)
__device__ uint32_t g_Ktfm[(size_t)NROWS * ND / 2];

__device__ __forceinline__ uint32_t f2tf32(float x) {
    uint32_t r;
    asm("cvt.rna.tf32.f32 %0, %1;" : "=r"(r) : "f"(x));
    return r;
}
__device__ __forceinline__ unsigned short bf16bits(float x) {
    return __bfloat16_as_ushort(__float2bfloat16(x));
}
__device__ __forceinline__ float bf16f(unsigned short u) {
    return __uint_as_float(((uint32_t)u) << 16);
}
__device__ __forceinline__ void packsplit(float a, float b, uint32_t& h, uint32_t& m) {
    unsigned short h0 = bf16bits(a), h1 = bf16bits(b);
    unsigned short m0 = bf16bits(a - bf16f(h0)), m1 = bf16bits(b - bf16f(h1));
    h = (uint32_t)h0 | ((uint32_t)h1 << 16);
    m = (uint32_t)m0 | ((uint32_t)m1 << 16);
}

#define MMA_TF32(d, a, b0, b1) \
    asm volatile("mma.sync.aligned.m16n8k8.row.col.f32.tf32.tf32.f32 " \
        "{%0,%1,%2,%3}, {%4,%5,%6,%7}, {%8,%9}, {%0,%1,%2,%3};" \
        : "+f"((d)[0]), "+f"((d)[1]), "+f"((d)[2]), "+f"((d)[3]) \
        : "r"((a)[0]), "r"((a)[1]), "r"((a)[2]), "r"((a)[3]), "r"(b0), "r"(b1))

#define MMA_BF16(d, a, b0, b1) \
    asm volatile("mma.sync.aligned.m16n8k16.row.col.f32.bf16.bf16.f32 " \
        "{%0,%1,%2,%3}, {%4,%5,%6,%7}, {%8,%9}, {%0,%1,%2,%3};" \
        : "+f"((d)[0]), "+f"((d)[1]), "+f"((d)[2]), "+f"((d)[3]) \
        : "r"((a)[0]), "r"((a)[1]), "r"((a)[2]), "r"((a)[3]), "r"(b0), "r"(b1))

// =====================================================================
// tf32 mma.sync GEMM: C(MxN) = A(MxK) @ W(NxK)^T + bias(N)
// =====================================================================
#define GPITCH 36
#define GASZ   (128 * GPITCH)
#define GSMEM  (4 * GASZ * 4)

__global__ void __launch_bounds__(256, 1) gemm_mma(
    const float* __restrict__ A, const float* __restrict__ Wm,
    const float* __restrict__ bias, float* __restrict__ C,
    int M, int N, int K)
{
    extern __shared__ uint32_t smg[];
    const int t    = threadIdx.x;
    const int wid  = t >> 5;
    const int lane = t & 31;
    const int wm   = wid & 1;
    const int wn   = wid >> 1;
    const int m0   = blockIdx.y * 128;
    const int n0   = blockIdx.x * 128;
    const int lr   = lane >> 2;
    const int lc   = lane & 3;

    const float* Ap = A  + (size_t)m0 * K;
    const float* Bp = Wm + (size_t)n0 * K;

    float acc[4][4][4];
#pragma unroll
    for (int i = 0; i < 4; i++)
#pragma unroll
        for (int j = 0; j < 4; j++)
#pragma unroll
            for (int x = 0; x < 4; x++) acc[i][j][x] = 0.f;

#pragma unroll
    for (int i = 0; i < 4; i++) {
        int idx = t + i * 256;
        int r = idx >> 3, c4 = idx & 7;
        float4 va = *(const float4*)(Ap + (size_t)r * K + c4 * 4);
        uint32_t* dst = &smg[r * GPITCH + c4 * 4];
        dst[0] = f2tf32(va.x); dst[1] = f2tf32(va.y);
        dst[2] = f2tf32(va.z); dst[3] = f2tf32(va.w);
        float4 vb = *(const float4*)(Bp + (size_t)r * K + c4 * 4);
        uint32_t* dstb = &smg[GASZ + r * GPITCH + c4 * 4];
        dstb[0] = f2tf32(vb.x); dstb[1] = f2tf32(vb.y);
        dstb[2] = f2tf32(vb.z); dstb[3] = f2tf32(vb.w);
    }
    __syncthreads();

    const int nkt = K >> 5;
    for (int kt = 0; kt < nkt; kt++) {
        const int cur = kt & 1;
        float4 ra[4], rb[4];
        if (kt + 1 < nkt) {
            const int ko = (kt + 1) * 32;
#pragma unroll
            for (int i = 0; i < 4; i++) {
                int idx = t + i * 256;
                int r = idx >> 3, c4 = idx & 7;
                ra[i] = *(const float4*)(Ap + (size_t)r * K + ko + c4 * 4);
                rb[i] = *(const float4*)(Bp + (size_t)r * K + ko + c4 * 4);
            }
        }
        const uint32_t* As = smg + cur * 2 * GASZ;
        const uint32_t* Bs = As + GASZ;
#pragma unroll
        for (int k8 = 0; k8 < 4; k8++) {
            const int kb = k8 * 8 + lc;
            uint32_t af[4][4], bf[4][2];
#pragma unroll
            for (int mt = 0; mt < 4; mt++) {
                int r = wm * 64 + mt * 16 + lr;
                af[mt][0] = As[r * GPITCH + kb];
                af[mt][1] = As[(r + 8) * GPITCH + kb];
                af[mt][2] = As[r * GPITCH + kb + 4];
                af[mt][3] = As[(r + 8) * GPITCH + kb + 4];
            }
#pragma unroll
            for (int nt = 0; nt < 4; nt++) {
                int n = wn * 32 + nt * 8 + lr;
                bf[nt][0] = Bs[n * GPITCH + kb];
                bf[nt][1] = Bs[n * GPITCH + kb + 4];
            }
#pragma unroll
            for (int mt = 0; mt < 4; mt++)
#pragma unroll
                for (int nt = 0; nt < 4; nt++)
                    MMA_TF32(acc[mt][nt], af[mt], bf[nt][0], bf[nt][1]);
        }
        if (kt + 1 < nkt) {
            uint32_t* dA = smg + (1 - cur) * 2 * GASZ;
            uint32_t* dB = dA + GASZ;
#pragma unroll
            for (int i = 0; i < 4; i++) {
                int idx = t + i * 256;
                int r = idx >> 3, c4 = idx & 7;
                uint32_t* da = &dA[r * GPITCH + c4 * 4];
                da[0] = f2tf32(ra[i].x); da[1] = f2tf32(ra[i].y);
                da[2] = f2tf32(ra[i].z); da[3] = f2tf32(ra[i].w);
                uint32_t* db = &dB[r * GPITCH + c4 * 4];
                db[0] = f2tf32(rb[i].x); db[1] = f2tf32(rb[i].y);
                db[2] = f2tf32(rb[i].z); db[3] = f2tf32(rb[i].w);
            }
        }
        __syncthreads();
    }

#pragma unroll
    for (int mt = 0; mt < 4; mt++) {
        int r = m0 + wm * 64 + mt * 16 + lr;
#pragma unroll
        for (int nt = 0; nt < 4; nt++) {
            int c = n0 + wn * 32 + nt * 8 + 2 * lc;
            float2 bv = *(const float2*)&bias[c];
            float2 o0, o1;
            o0.x = acc[mt][nt][0] + bv.x; o0.y = acc[mt][nt][1] + bv.y;
            o1.x = acc[mt][nt][2] + bv.x; o1.y = acc[mt][nt][3] + bv.y;
            *(float2*)&C[(size_t)r * N + c]       = o0;
            *(float2*)&C[(size_t)(r + 8) * N + c] = o1;
        }
    }
}

// =====================================================================
// beta[row] = 1 / (||K_row||^2 + 1e-6)
// =====================================================================
__global__ void __launch_bounds__(256) beta_kernel()
{
    int row  = blockIdx.x * 8 + (threadIdx.x >> 5);
    int lane = threadIdx.x & 31;
    const float* p = g_K + (size_t)row * ND;
    float s = 0.f;
#pragma unroll
    for (int i = 0; i < 8; i++) {
        float4 v = *(const float4*)&p[lane * 4 + i * 128];
        s += v.x * v.x + v.y * v.y + v.z * v.z + v.w * v.w;
    }
#pragma unroll
    for (int o = 16; o; o >>= 1) s += __shfl_xor_sync(0xffffffffu, s, o);
    if (lane == 0) g_beta[row] = 1.f / (s + 1e-6f);
}

// =====================================================================
// prep: per (batch, chunk) block.
// emits: A (row-major fp32), U (g_V), and bf16 2-plane fragments:
// Qfh/Qfm, Wfh/Wfm (negated), Ktfh/Ktfm.
// =====================================================================
#define PPAD 35
__global__ void __launch_bounds__(256) prep_kernel()
{
    __shared__ float sA[64 * PPAD];
    __shared__ float sB[64 * PPAD];
    __shared__ float T_s[64 * 64];
    __shared__ float rowtmp[64];
    __shared__ float beta_s[64];

    const int t  = threadIdx.x;
    const int bc = blockIdx.x;
    const size_t row0 = (size_t)(bc >> 6) * NL + (size_t)(bc & 63) * 64;
    const size_t fb   = (size_t)bc * 32768;   // frag plane base (uint32)

    if (t < 64) beta_s[t] = g_beta[row0 + t];
    __syncthreads();

    const int i0  = (t >> 4) * 4;
    const int j0  = (t & 15) * 4;
    const int lkk = t & 31, ljr = t >> 5;
    const int lane = t & 31, flr = lane >> 2, flc = lane & 3;
    const int grp  = t >> 5;

    float ga[4][4], qa[4][4];
#pragma unroll
    for (int a = 0; a < 4; a++)
#pragma unroll
        for (int b = 0; b < 4; b++) { ga[a][b] = 0.f; qa[a][b] = 0.f; }

    for (int k0 = 0; k0 < ND; k0 += 32) {
#pragma unroll
        for (int h = 0; h < 8; h++) {
            int j = ljr + h * 8;
            sA[j * PPAD + lkk] = g_K[(row0 + j) * ND + k0 + lkk];
            sB[j * PPAD + lkk] = g_Q[(row0 + j) * ND + k0 + lkk];
        }
        __syncthreads();

        // ---- emit Q fragments (A-operand, 2 k16 x 4 mg groups) ----
        {
            int k16l = grp >> 2, mg = grp & 3;
            int r0 = mg * 16 + flr;
            int kb = k16l * 16 + 2 * flc;
            uint32_t ah[4], am[4];
            packsplit(sB[r0 * PPAD + kb],           sB[r0 * PPAD + kb + 1],           ah[0], am[0]);
            packsplit(sB[(r0 + 8) * PPAD + kb],     sB[(r0 + 8) * PPAD + kb + 1],     ah[1], am[1]);
            packsplit(sB[r0 * PPAD + kb + 8],       sB[r0 * PPAD + kb + 9],           ah[2], am[2]);
            packsplit(sB[(r0 + 8) * PPAD + kb + 8], sB[(r0 + 8) * PPAD + kb + 9],     ah[3], am[3]);
            size_t o = fb + (size_t)(((k0 >> 4) + k16l) * 4 + mg) * 128 + lane * 4;
            *(uint4*)&g_Qfh[o] = make_uint4(ah[0], ah[1], ah[2], ah[3]);
            *(uint4*)&g_Qfm[o] = make_uint4(am[0], am[1], am[2], am[3]);
        }
        // ---- emit K fragments (B-operand) ----
#pragma unroll
        for (int h = 0; h < 2; h++) {
            int g2 = grp + h * 8;
            int ngl = g2 & 3, j16 = g2 >> 2;
            int nn = ngl * 8 + flr;
            int jb = j16 * 16 + 2 * flc;
            uint32_t bh0, bm0, bh1, bm1;
            packsplit(sA[jb * PPAD + nn],       sA[(jb + 1) * PPAD + nn], bh0, bm0);
            packsplit(sA[(jb + 8) * PPAD + nn], sA[(jb + 9) * PPAD + nn], bh1, bm1);
            size_t o = fb + (size_t)(((k0 >> 3) + ngl) * 4 + j16) * 64 + lane * 2;
            *(uint2*)&g_Ktfh[o] = make_uint2(bh0, bh1);
            *(uint2*)&g_Ktfm[o] = make_uint2(bm0, bm1);
        }

#pragma unroll
        for (int kk = 0; kk < 32; kk++) {
            float ki[4], kj[4], qi[4];
#pragma unroll
            for (int a = 0; a < 4; a++) {
                ki[a] = sA[(i0 + a) * PPAD + kk];
                qi[a] = sB[(i0 + a) * PPAD + kk];
                kj[a] = sA[(j0 + a) * PPAD + kk];
            }
#pragma unroll
            for (int a = 0; a < 4; a++)
#pragma unroll
                for (int b = 0; b < 4; b++) {
                    ga[a][b] += ki[a] * kj[b];
                    qa[a][b] += qi[a] * kj[b];
                }
        }
        __syncthreads();
    }

    float* Aout = g_A + (size_t)bc * 4096;
#pragma unroll
    for (int a = 0; a < 4; a++)
#pragma unroll
        for (int b = 0; b < 4; b++) {
            int i = i0 + a, j = j0 + b;
            T_s[i * 64 + j]  = (j < i) ? (-beta_s[i] * ga[a][b]) : 0.f;
            Aout[i * 64 + j] = (j <= i) ? qa[a][b] : 0.f;
        }
    __syncthreads();

    for (int i = 1; i < 64; i++) {
        if (t < i) rowtmp[t] = T_s[i * 64 + t];
        __syncthreads();
        if (t < i) {
            float s = 0.f;
            for (int j = t + 1; j < i; j++) s += rowtmp[j] * T_s[j * 64 + t];
            T_s[i * 64 + t] += s;
        }
        __syncthreads();
    }
    if (t < 64) T_s[t * 64 + t] += 1.f;
    __syncthreads();

    const int ip = (t >> 4) * 4;
    const int dp = (t & 15) * 2;
    for (int d0 = 0; d0 < ND; d0 += 32) {
#pragma unroll
        for (int h = 0; h < 8; h++) {
            int j = ljr + h * 8;
            float bj = beta_s[j];
            sA[j * PPAD + lkk] = g_K[(row0 + j) * ND + d0 + lkk] * bj;
            sB[j * PPAD + lkk] = g_V[(row0 + j) * ND + d0 + lkk] * bj;
        }
        __syncthreads();
        float wv[4][2], uv[4][2];
#pragma unroll
        for (int a = 0; a < 4; a++) { wv[a][0] = wv[a][1] = 0.f; uv[a][0] = uv[a][1] = 0.f; }
#pragma unroll
        for (int j = 0; j < 64; j++) {
            float kb0 = sA[j * PPAD + dp], kb1 = sA[j * PPAD + dp + 1];
            float vb0 = sB[j * PPAD + dp], vb1 = sB[j * PPAD + dp + 1];
#pragma unroll
            for (int a = 0; a < 4; a++) {
                float tv = T_s[(ip + a) * 64 + j];
                wv[a][0] += tv * kb0; wv[a][1] += tv * kb1;
                uv[a][0] += tv * vb0; uv[a][1] += tv * vb1;
            }
        }
#pragma unroll
        for (int a = 0; a < 4; a++) {
            size_t off = (row0 + ip + a) * ND + d0 + dp;
            *(float2*)&g_V[off] = make_float2(uv[a][0], uv[a][1]);
        }
        __syncthreads();
#pragma unroll
        for (int a = 0; a < 4; a++) {
            sA[(ip + a) * PPAD + dp]     = -wv[a][0];
            sA[(ip + a) * PPAD + dp + 1] = -wv[a][1];
        }
        __syncthreads();
        // emit -W fragments (A-operand)
        {
            int k16l = grp >> 2, mg = grp & 3;
            int r0 = mg * 16 + flr;
            int kb = k16l * 16 + 2 * flc;
            uint32_t ah[4], am[4];
            packsplit(sA[r0 * PPAD + kb],           sA[r0 * PPAD + kb + 1],       ah[0], am[0]);
            packsplit(sA[(r0 + 8) * PPAD + kb],     sA[(r0 + 8) * PPAD + kb + 1], ah[1], am[1]);
            packsplit(sA[r0 * PPAD + kb + 8],       sA[r0 * PPAD + kb + 9],       ah[2], am[2]);
            packsplit(sA[(r0 + 8) * PPAD + kb + 8], sA[(r0 + 8) * PPAD + kb + 9], ah[3], am[3]);
            size_t o = fb + (size_t)(((d0 >> 4) + k16l) * 4 + mg) * 128 + lane * 4;
            *(uint4*)&g_Wfh[o] = make_uint4(ah[0], ah[1], ah[2], ah[3]);
            *(uint4*)&g_Wfm[o] = make_uint4(am[0], am[1], am[2], am[3]);
        }
        __syncthreads();
    }
}

// =====================================================================
// scan (tensor, bf16x3, dual independent column-halves per CTA)
// grid (32 colblocks, 8 batches), 512 thr. Each 256-thread half owns 16
// columns; halves sync via named barriers (bar.sync 1/2, 256).
// =====================================================================
#define SP 516                  // S plane pitch in uint32 (mod 32 == 4)
#define UP 36                   // u plane pitch in uint32 (mod 32 == 4)
#define OFF_SM (32 * SP * 4)
#define OFF_SL (2 * 32 * SP * 4)
#define OFF_UH (3 * 32 * SP * 4)
#define OFF_UM (OFF_UH + 32 * UP * 4)
#define SCAN_SMEM3 (OFF_UM + 32 * UP * 4)   // 207360

#define BARH() asm volatile("bar.sync %0, 256;" :: "r"(1 + half) : "memory")

__global__ void __launch_bounds__(512, 1) scan_tc()
{
    extern __shared__ char smc[];
    uint32_t* ShP = (uint32_t*)smc;
    uint32_t* SmP = (uint32_t*)(smc + OFF_SM);
    uint32_t* SlP = (uint32_t*)(smc + OFF_SL);
    uint32_t* UhP = (uint32_t*)(smc + OFF_UH);
    uint32_t* UmP = (uint32_t*)(smc + OFF_UM);
    unsigned short* Uh16 = (unsigned short*)UhP;
    unsigned short* Um16 = (unsigned short*)UmP;

    const int t    = threadIdx.x;
    const int half = t >> 8;          // 0 / 1: independent column half
    const int t2   = t & 255;
    const int lane = t & 31;
    const int wid2 = t2 >> 5;         // warp id within half (0..7)
    const int lr   = lane >> 2;
    const int lc   = lane & 3;
    const int b    = blockIdx.y;
    const int cb0  = blockIdx.x * 32 + half * 16;   // global column base
    const int colb = half * 16;                     // smem column base

    for (int i = t; i < 32 * SP; i += 512) { ShP[i] = 0u; SmP[i] = 0u; SlP[i] = 0u; }
    __syncthreads();

    const int  mg  = wid2 & 3;
    const bool isQ = (wid2 >= 4);
    const int  dn  = wid2 * 128;      // phase d kdim slice base

    for (int n = 0; n < 64; n++) {
        const size_t row0  = (size_t)b * NL + (size_t)n * 64;
        const size_t cbase = (size_t)b * 64 + n;

        // ---------------- phase b: u = U0 - W@S ; qs = Q@S ----------------
        float acc[2][4];
        if (!isQ) {
            const size_t rr = row0 + mg * 16 + lr;
#pragma unroll
            for (int nt = 0; nt < 2; nt++) {
                int cc = cb0 + nt * 8 + 2 * lc;
                float2 v0 = *(const float2*)&g_V[rr * ND + cc];
                float2 v1 = *(const float2*)&g_V[(rr + 8) * ND + cc];
                acc[nt][0] = v0.x; acc[nt][1] = v0.y;
                acc[nt][2] = v1.x; acc[nt][3] = v1.y;
            }
        } else {
#pragma unroll
            for (int nt = 0; nt < 2; nt++)
#pragma unroll
                for (int x = 0; x < 4; x++) acc[nt][x] = 0.f;
        }
        {
            const uint32_t* Afh = (isQ ? g_Qfh : g_Wfh) + cbase * 32768;
            const uint32_t* Afm = (isQ ? g_Qfm : g_Wfm) + cbase * 32768;
#pragma unroll 2
            for (int k16 = 0; k16 < 64; k16++) {
                uint4 h4 = *(const uint4*)&Afh[(size_t)(k16 * 4 + mg) * 128 + lane * 4];
                uint4 m4 = *(const uint4*)&Afm[(size_t)(k16 * 4 + mg) * 128 + lane * 4];
                uint32_t ah[4] = {h4.x, h4.y, h4.z, h4.w};
                uint32_t am[4] = {m4.x, m4.y, m4.z, m4.w};
#pragma unroll
                for (int nt = 0; nt < 2; nt++) {
                    int base = (colb + nt * 8 + lr) * SP + k16 * 8 + lc;
                    uint32_t bh0 = ShP[base], bh1 = ShP[base + 4];
                    uint32_t bm0 = SmP[base], bm1 = SmP[base + 4];
                    MMA_BF16(acc[nt], ah, bh0, bh1);
                    MMA_BF16(acc[nt], ah, bm0, bm1);
                    MMA_BF16(acc[nt], am, bh0, bh1);
                }
            }
        }
        // u-warps: write u^T hi/mid planes
        if (!isQ) {
#pragma unroll
            for (int nt = 0; nt < 2; nt++) {
#pragma unroll
                for (int x = 0; x < 4; x++) {
                    int cc = colb + nt * 8 + 2 * lc + (x & 1);
                    int j  = mg * 16 + lr + ((x >> 1) << 3);
                    float v = acc[nt][x];
                    unsigned short h = bf16bits(v);
                    Uh16[cc * 72 + j] = h;
                    Um16[cc * 72 + j] = bf16bits(v - bf16f(h));
                }
            }
        }
        BARH();

        // ---------------- phase c (q-warps): O = A@u + qs ----------------
        if (isQ) {
            const float* Ab = g_A + cbase * 4096;
#pragma unroll
            for (int j16 = 0; j16 < 4; j16++) {
                const float* ar0 = &Ab[(mg * 16 + lr) * 64 + j16 * 16 + 2 * lc];
                const float* ar1 = ar0 + 8 * 64;
                float2 p0 = *(const float2*)ar0;
                float2 p1 = *(const float2*)ar1;
                float2 p2 = *(const float2*)(ar0 + 8);
                float2 p3 = *(const float2*)(ar1 + 8);
                uint32_t ah[4], am[4];
                packsplit(p0.x, p0.y, ah[0], am[0]);
                packsplit(p1.x, p1.y, ah[1], am[1]);
                packsplit(p2.x, p2.y, ah[2], am[2]);
                packsplit(p3.x, p3.y, ah[3], am[3]);
#pragma unroll
                for (int nt = 0; nt < 2; nt++) {
                    int base = (colb + nt * 8 + lr) * UP + j16 * 8 + lc;
                    uint32_t bh0 = UhP[base], bh1 = UhP[base + 4];
                    uint32_t bm0 = UmP[base], bm1 = UmP[base + 4];
                    MMA_BF16(acc[nt], ah, bh0, bh1);
                    MMA_BF16(acc[nt], ah, bm0, bm1);
                    MMA_BF16(acc[nt], am, bh0, bh1);
                }
            }
            const size_t rr = row0 + mg * 16 + lr;
#pragma unroll
            for (int nt = 0; nt < 2; nt++) {
                int cc = cb0 + nt * 8 + 2 * lc;
                *(float2*)&g_O[rr * ND + cc]       = make_float2(acc[nt][0], acc[nt][1]);
                *(float2*)&g_O[(rr + 8) * ND + cc] = make_float2(acc[nt][2], acc[nt][3]);
            }
        }

        // ------- phase d: S += K^T@u  (dS^T = u^T @ K, kdim sliced) -------
        {
            const uint32_t* Kfh = g_Ktfh + cbase * 32768;
            const uint32_t* Kfm = g_Ktfm + cbase * 32768;
            const int ng0 = dn >> 3;   // wid2*16
#pragma unroll 2
            for (int ng = 0; ng < 16; ng++) {
                float dacc[4] = {0.f, 0.f, 0.f, 0.f};
#pragma unroll
                for (int j16 = 0; j16 < 4; j16++) {
                    int b0 = (colb + lr) * UP + j16 * 8 + lc;
                    int b1 = (colb + lr + 8) * UP + j16 * 8 + lc;
                    uint32_t ah[4] = {UhP[b0], UhP[b1], UhP[b0 + 4], UhP[b1 + 4]};
                    uint32_t am[4] = {UmP[b0], UmP[b1], UmP[b0 + 4], UmP[b1 + 4]};
                    size_t fo = (size_t)((ng0 + ng) * 4 + j16) * 64 + lane * 2;
                    uint2 kh = *(const uint2*)&Kfh[fo];
                    uint2 km = *(const uint2*)&Kfm[fo];
                    MMA_BF16(dacc, ah, kh.x, kh.y);
                    MMA_BF16(dacc, ah, km.x, km.y);
                    MMA_BF16(dacc, am, kh.x, kh.y);
                }
#pragma unroll
                for (int h8 = 0; h8 < 2; h8++) {
                    int cc = colb + lr + h8 * 8;
                    int widx = cc * SP + (dn >> 1) + ng * 4 + lc;
                    uint32_t wh = ShP[widx], wm = SmP[widx], wl = SlP[widx];
                    float s0 = bf16f((unsigned short)(wh & 0xFFFF))
                             + bf16f((unsigned short)(wm & 0xFFFF))
                             + bf16f((unsigned short)(wl & 0xFFFF)) + dacc[h8 * 2];
                    float s1 = bf16f((unsigned short)(wh >> 16))
                             + bf16f((unsigned short)(wm >> 16))
                             + bf16f((unsigned short)(wl >> 16)) + dacc[h8 * 2 + 1];
                    unsigned short h0 = bf16bits(s0); float r0 = s0 - bf16f(h0);
                    unsigned short m0 = bf16bits(r0);
                    unsigned short l0 = bf16bits(r0 - bf16f(m0));
                    unsigned short h1 = bf16bits(s1); float r1 = s1 - bf16f(h1);
                    unsigned short m1 = bf16bits(r1);
                    unsigned short l1 = bf16bits(r1 - bf16f(m1));
                    ShP[widx] = (uint32_t)h0 | ((uint32_t)h1 << 16);
                    SmP[widx] = (uint32_t)m0 | ((uint32_t)m1 << 16);
                    SlP[widx] = (uint32_t)l0 | ((uint32_t)l1 << 16);
                }
            }
        }
        BARH();
    }
}

// =====================================================================
extern "C" void kernel_launch(void* const* d_in, const int* in_sizes, int n_in,
                              void* d_out, int out_size)
{
    int base = 1;
    if (n_in >= 10 && in_sizes[1] == 1) base = 2;
    const float* X    = (const float*)d_in[0];
    const float* Wq_w = (const float*)d_in[base + 0];
    const float* Wq_b = (const float*)d_in[base + 1];
    const float* Wk_w = (const float*)d_in[base + 2];
    const float* Wk_b = (const float*)d_in[base + 3];
    const float* Wv_w = (const float*)d_in[base + 4];
    const float* Wv_b = (const float*)d_in[base + 5];
    const float* Wo_w = (const float*)d_in[base + 6];
    const float* Wo_b = (const float*)d_in[base + 7];
    float* out = (float*)d_out;

    float *pQ, *pK, *pV, *pO;
    cudaGetSymbolAddress((void**)&pQ, g_Q);
    cudaGetSymbolAddress((void**)&pK, g_K);
    cudaGetSymbolAddress((void**)&pV, g_V);
    cudaGetSymbolAddress((void**)&pO, g_O);

    cudaFuncSetAttribute(gemm_mma, cudaFuncAttributeMaxDynamicSharedMemorySize, GSMEM);
    dim3 gg(ND / 128, NROWS / 128);
    gemm_mma<<<gg, 256, GSMEM>>>(X, Wq_w, Wq_b, pQ, NROWS, ND, ND);
    gemm_mma<<<gg, 256, GSMEM>>>(X, Wk_w, Wk_b, pK, NROWS, ND, ND);
    gemm_mma<<<gg, 256, GSMEM>>>(X, Wv_w, Wv_b, pV, NROWS, ND, ND);
    beta_kernel<<<NROWS / 8, 256>>>();
    prep_kernel<<<NB * 64, 256>>>();
    cudaFuncSetAttribute(scan_tc, cudaFuncAttributeMaxDynamicSharedMemorySize, SCAN_SMEM3);
    scan_tc<<<dim3(32, NB), 512, SCAN_SMEM3>>>();   // FIX: 32 col-blocks, not 16
    gemm_mma<<<gg, 256, GSMEM>>>(pO, Wo_w, Wo_b, out, NROWS, ND, ND);
}